// round 10
// baseline (speedup 1.0000x reference)
#include <cuda_runtime.h>
#include <cuda.h>
#include <math.h>

#define Hh 512
#define Ww 512
#define Ss 5
#define Cin 2
#define Cout 2

#define TW 128
#define TH 16
#define ROWS (TH + 2)     // 18
#define NPLANES 10
#define RSTRIDE 136       // smem col i <-> global col w_base-4+i ; interior 4..131, halos 3 / 132
#define PLANE (ROWS * RSTRIDE)                  // 2448 floats
#define TILE_BYTES (NPLANES * PLANE * 4)        // 97920
#define TILE_OFF 1024
#define SMEM_BYTES (TILE_OFF + TILE_BYTES)      // 98944

extern __shared__ __align__(1024) char smem_arena[];

__global__ __launch_bounds__(512, 2)
void snn_fused8(const __grid_constant__ CUtensorMap tmap,
                const float* __restrict__ conv_w,
                const float* __restrict__ conv_b,
                const float* __restrict__ gamma,
                const float* __restrict__ beta_bn,
                const float* __restrict__ run_mean,
                const float* __restrict__ run_var,
                const float* __restrict__ rho,
                float* __restrict__ out)
{
    // arena: [0,8) mbar ; [64,256) wrow[(c*2+o)*3+r] as float4 (12 rows) ;
    //        [256,264) sb ; [264,272) sad ; [1024,...) tile
    unsigned long long* mbar = (unsigned long long*)smem_arena;
    float4* wrow = (float4*)(smem_arena + 64);
    float*  sb   = (float*)(smem_arena + 256);
    float*  sad  = (float*)(smem_arena + 264);
    float*  tile = (float*)(smem_arena + TILE_OFF);

    const int tx  = threadIdx.x;          // 0..31
    const int ty  = threadIdx.y;          // 0..15
    const int tid = ty * 32 + tx;
    const int b      = blockIdx.z;
    const int h_base = blockIdx.y * TH;
    const int w_base = blockIdx.x * TW;

    unsigned int mbar_a, tile_a;
    asm("{ .reg .u64 t; cvta.to.shared.u64 t, %1; cvt.u32.u64 %0, t; }"
        : "=r"(mbar_a) : "l"(mbar));
    asm("{ .reg .u64 t; cvta.to.shared.u64 t, %1; cvt.u32.u64 %0, t; }"
        : "=r"(tile_a) : "l"(tile));

    if (tid == 0) {
        asm volatile("mbarrier.init.shared.b64 [%0], 1;" :: "r"(mbar_a) : "memory");
    }
    // folded weight rows: 12 threads each build one float4 row
    if (tid >= 32 && tid < 32 + 12) {
        int i = tid - 32;          // (c*2+o)*3 + r
        int r = i % 3;
        int co = i / 3;            // c*2+o
        int c = co >> 1;
        int o = co & 1;
        float inv = gamma[o] * rsqrtf(run_var[o] + 1e-5f);
        const float* wsrc = conv_w + (o * Cin + c) * 9 + r * 3;
        wrow[i] = make_float4(wsrc[0] * inv, wsrc[1] * inv, wsrc[2] * inv, 0.f);
    }
    if (tid >= 64 && tid < 64 + Cout) {
        int o = tid - 64;
        float inv = gamma[o] * rsqrtf(run_var[o] + 1e-5f);
        sb[o]  = (conv_b[o] - run_mean[o]) * inv + beta_bn[o];
        float rc = fminf(fmaxf(rho[o], 0.032f), 0.055f);
        sad[o] = expf(-0.05f / rc);
    }
    __syncthreads();

    // ---- one bulk TMA: box (136 x 18 x 10) f32 ----
    if (tid == 0) {
        asm volatile("mbarrier.arrive.expect_tx.shared.b64 _, [%0], %1;"
                     :: "r"(mbar_a), "r"((unsigned)TILE_BYTES) : "memory");
        int cx = w_base - 4;
        int cy = h_base - 1;
        int cz = b * NPLANES;
        asm volatile(
            "cp.async.bulk.tensor.3d.shared::cta.global.tile.mbarrier::complete_tx::bytes "
            "[%0], [%1, {%2, %3, %4}], [%5];"
            :: "r"(tile_a), "l"(&tmap), "r"(cx), "r"(cy), "r"(cz), "r"(mbar_a)
            : "memory");
    }
    {
        unsigned int done;
        asm volatile(
            "{\n\t.reg .pred p;\n\t"
            "mbarrier.try_wait.parity.acquire.cta.shared::cta.b64 p, [%1], 0;\n\t"
            "selp.b32 %0, 1, 0, p;\n\t}"
            : "=r"(done) : "r"(mbar_a) : "memory");
        if (!done) {
            asm volatile(
                "{\n\t.reg .pred P1;\n\t"
                "WL_%=:\n\t"
                "mbarrier.try_wait.parity.acquire.cta.shared::cta.b64 P1, [%0], 0, 0x989680;\n\t"
                "@P1 bra.uni WD_%=;\n\t"
                "bra.uni WL_%=;\n\t"
                "WD_%=:\n\t}"
                :: "r"(mbar_a) : "memory");
        }
    }

    const size_t img = (size_t)Hh * Ww;
    const int P = 4 * tx;
    const int h0 = h_base + ty;
    const size_t opix = (size_t)h0 * Ww + w_base + P;

    const float sb0 = sb[0], sb1 = sb[1];
    const float ad0 = sad[0], ad1 = sad[1];

    float mem[Cout][4], aa[Cout][4];
    #pragma unroll
    for (int o = 0; o < Cout; o++)
        #pragma unroll
        for (int k = 0; k < 4; k++) { mem[o][k] = 0.f; aa[o][k] = 0.f; }

    #pragma unroll
    for (int s = 0; s < Ss; s++) {
        // acc initialized with folded bias (saves one FADD per px later)
        float acc[Cout][4];
        #pragma unroll
        for (int k = 0; k < 4; k++) { acc[0][k] = sb0; acc[1][k] = sb1; }

        #pragma unroll
        for (int c = 0; c < Cin; c++) {
            const int p = s * 2 + c;
            const float* pl = &tile[p * PLANE + ty * RSTRIDE];
            #pragma unroll
            for (int r = 0; r < 3; r++) {
                const float* rp = pl + r * RSTRIDE;
                float4 B4 = *(const float4*)(rp + 4 + P);             // cols P+4..P+7
                float left  = __shfl_up_sync(0xffffffffu, B4.w, 1);   // col P+3
                float right = __shfl_down_sync(0xffffffffu, B4.x, 1); // col P+8
                if (tx == 0)  left  = rp[3];
                if (tx == 31) right = rp[132];
                #pragma unroll
                for (int o = 0; o < Cout; o++) {
                    float4 w = wrow[(c * 2 + o) * 3 + r];   // one LDS.128 broadcast
                    float a0 = acc[o][0], a1 = acc[o][1], a2 = acc[o][2], a3 = acc[o][3];
                    a0 = fmaf(left, w.x, a0); a0 = fmaf(B4.x, w.y, a0); a0 = fmaf(B4.y, w.z, a0);
                    a1 = fmaf(B4.x, w.x, a1); a1 = fmaf(B4.y, w.y, a1); a1 = fmaf(B4.z, w.z, a1);
                    a2 = fmaf(B4.y, w.x, a2); a2 = fmaf(B4.z, w.y, a2); a2 = fmaf(B4.w, w.z, a2);
                    a3 = fmaf(B4.z, w.x, a3); a3 = fmaf(B4.w, w.y, a3); a3 = fmaf(right, w.z, a3);
                    acc[o][0] = a0; acc[o][1] = a1; acc[o][2] = a2; acc[o][3] = a3;
                }
            }
        }

        // recurrence + streaming store
        #pragma unroll
        for (int o = 0; o < Cout; o++) {
            const float ad = (o == 0) ? ad0 : ad1;
            float spk[4];
            #pragma unroll
            for (int k = 0; k < 4; k++) {
                float m   = mem[o][k] + acc[o][k];
                float Ath = fmaf(0.07f, aa[o][k], 0.3f);
                bool  p   = (m > Ath);
                float sv  = p ? 1.f : 0.f;
                float md  = m * 0.2f;
                mem[o][k] = p ? 0.f : md;
                aa[o][k]  = fmaf(ad, aa[o][k], sv);
                spk[k] = sv;
            }
            float4 v4 = make_float4(spk[0], spk[1], spk[2], spk[3]);
            __stcs((float4*)(out + ((size_t)(b * 10 + s * 2 + o)) * img + opix), v4);
        }
    }
}

typedef CUresult (CUDAAPI *PFN_encodeTiled_local)(
    CUtensorMap*, CUtensorMapDataType, cuuint32_t, void*,
    const cuuint64_t*, const cuuint64_t*, const cuuint32_t*, const cuuint32_t*,
    CUtensorMapInterleave, CUtensorMapSwizzle, CUtensorMapL2promotion,
    CUtensorMapFloatOOBfill);

extern "C" void kernel_launch(void* const* d_in, const int* in_sizes, int n_in,
                              void* d_out, int out_size)
{
    const float* all_input = (const float*)d_in[0];
    const float* conv_w    = (const float*)d_in[1];
    const float* conv_b    = (const float*)d_in[2];
    const float* gamma     = (const float*)d_in[3];
    const float* beta_bn   = (const float*)d_in[4];
    const float* run_mean  = (const float*)d_in[5];
    const float* run_var   = (const float*)d_in[6];
    const float* rho       = (const float*)d_in[7];
    float* out = (float*)d_out;

    PFN_encodeTiled_local encode = nullptr;
    cudaDriverEntryPointQueryResult qr;
    cudaGetDriverEntryPoint("cuTensorMapEncodeTiled", (void**)&encode,
                            cudaEnableDefault, &qr);

    CUtensorMap tmap;
    {
        cuuint64_t dims[3]    = { (cuuint64_t)Ww, (cuuint64_t)Hh,
                                  (cuuint64_t)(16 * NPLANES) };
        cuuint64_t strides[2] = { (cuuint64_t)Ww * 4,
                                  (cuuint64_t)Hh * Ww * 4 };
        cuuint32_t box[3]     = { (cuuint32_t)RSTRIDE, (cuuint32_t)ROWS,
                                  (cuuint32_t)NPLANES };
        cuuint32_t estr[3]    = { 1, 1, 1 };
        encode(&tmap, CU_TENSOR_MAP_DATA_TYPE_FLOAT32, 3, (void*)all_input,
               dims, strides, box, estr,
               CU_TENSOR_MAP_INTERLEAVE_NONE, CU_TENSOR_MAP_SWIZZLE_NONE,
               CU_TENSOR_MAP_L2_PROMOTION_L2_128B,
               CU_TENSOR_MAP_FLOAT_OOB_FILL_NONE);
    }

    cudaFuncSetAttribute(snn_fused8,
                         cudaFuncAttributeMaxDynamicSharedMemorySize, SMEM_BYTES);

    dim3 block(32, TH, 1);                 // 512 threads
    dim3 grid(Ww / TW, Hh / TH, 16);       // 2048 blocks
    snn_fused8<<<grid, block, SMEM_BYTES>>>(tmap, conv_w, conv_b, gamma, beta_bn,
                                            run_mean, run_var, rho, out);
}